// round 1
// baseline (speedup 1.0000x reference)
#include <cuda_runtime.h>
#include <math.h>

#define Bn 64
#define Dn 8732
#define On 16
#define Cn 81
#define THRESH 0.5f

// ---- device scratch (no allocations allowed) ----
__device__ float g_loc_sum;
__device__ float g_conf_pos;
__device__ float g_conf_neg;
__device__ int   g_npos_tot;
__device__ int   g_npos[Bn];
__device__ float g_negce[Bn * Dn];
__device__ unsigned char g_tcls[Bn * Dn];

__global__ void k_init() {
    g_loc_sum = 0.f; g_conf_pos = 0.f; g_conf_neg = 0.f; g_npos_tot = 0;
}

// One block per batch element. Computes matching, target classes, and the
// (fused) SmoothL1 localization loss contribution.
__global__ __launch_bounds__(512) void k_match(const float* __restrict__ locs_pred,
                                               const float* __restrict__ boxes,
                                               const int*   __restrict__ labels,
                                               const float* __restrict__ dboxes) {
    __shared__ float s_ov[Dn];
    __shared__ unsigned char s_obj[Dn];
    __shared__ float s_bx[On][4];
    __shared__ float s_area[On];
    __shared__ int   s_lab[On];
    __shared__ float s_redv[On * 16];
    __shared__ int   s_redi[On * 16];
    __shared__ int   s_dobj[On];
    __shared__ float s_rs[16];
    __shared__ int   s_rc[16];

    const int b = blockIdx.x;
    const int tid = threadIdx.x;
    const int warp = tid >> 5, lane = tid & 31;

    if (tid < On * 4) ((float*)s_bx)[tid] = boxes[b * On * 4 + tid];
    if (tid < On)     s_lab[tid] = labels[b * On + tid];
    __syncthreads();
    if (tid < On) s_area[tid] = (s_bx[tid][2] - s_bx[tid][0]) * (s_bx[tid][3] - s_bx[tid][1]);
    __syncthreads();

    // local per-object best (over defaults)
    float lv[On]; int li[On];
#pragma unroll
    for (int o = 0; o < On; o++) { lv[o] = -1.f; li[o] = 0x7fffffff; }

    for (int d = tid; d < Dn; d += 512) {
        float4 db = ((const float4*)dboxes)[d];
        float dx1 = db.x - db.z * 0.5f, dy1 = db.y - db.w * 0.5f;
        float dx2 = db.x + db.z * 0.5f, dy2 = db.y + db.w * 0.5f;
        float darea = db.z * db.w;
        float bestv = -1.f; int besto = 0;
#pragma unroll
        for (int o = 0; o < On; o++) {
            float ix = fminf(s_bx[o][2], dx2) - fmaxf(s_bx[o][0], dx1);
            float iy = fminf(s_bx[o][3], dy2) - fmaxf(s_bx[o][1], dy1);
            ix = fmaxf(ix, 0.f); iy = fmaxf(iy, 0.f);
            float inter = ix * iy;
            float iou = inter / (s_area[o] + darea - inter);
            if (iou > bestv) { bestv = iou; besto = o; }       // first-max semantics over o
            if (iou > lv[o]) { lv[o] = iou; li[o] = d; }       // ascending d -> first-max over d
        }
        s_ov[d] = bestv;
        s_obj[d] = (unsigned char)besto;
    }

    // reduce per-object best across threads (tie -> smaller default index)
#pragma unroll
    for (int o = 0; o < On; o++) {
        float v = lv[o]; int i = li[o];
        for (int off = 16; off; off >>= 1) {
            float ov = __shfl_down_sync(0xffffffffu, v, off);
            int   oi = __shfl_down_sync(0xffffffffu, i, off);
            if (ov > v || (ov == v && oi < i)) { v = ov; i = oi; }
        }
        if (lane == 0) { s_redv[o * 16 + warp] = v; s_redi[o * 16 + warp] = i; }
    }
    __syncthreads();
    if (tid < On) {
        float v = s_redv[tid * 16]; int i = s_redi[tid * 16];
        for (int w = 1; w < 16; w++) {
            float ov = s_redv[tid * 16 + w]; int oi = s_redi[tid * 16 + w];
            if (ov > v || (ov == v && oi < i)) { v = ov; i = oi; }
        }
        s_dobj[tid] = i;
    }
    __syncthreads();
    if (tid == 0) {
        for (int o = 0; o < On; o++) {
            int d = s_dobj[o];
            s_obj[d] = (unsigned char)o;
            s_ov[d] = 1.f;
        }
    }
    __syncthreads();

    // targets + fused SmoothL1 on positives
    float lsum = 0.f; int lcnt = 0;
    for (int d = tid; d < Dn; d += 512) {
        int o = s_obj[d];
        float ov = s_ov[d];
        int lab = (ov < THRESH) ? 0 : s_lab[o];
        g_tcls[b * Dn + d] = (unsigned char)lab;
        if (lab != 0) {
            lcnt++;
            float4 db = ((const float4*)dboxes)[d];
            float bx1 = s_bx[o][0], by1 = s_bx[o][1], bx2 = s_bx[o][2], by2 = s_bx[o][3];
            float cx = 0.5f * (bx1 + bx2), cy = 0.5f * (by1 + by2);
            float w = bx2 - bx1, h = by2 - by1;
            float t0 = (cx - db.x) / (db.z * 0.1f);
            float t1 = (cy - db.y) / (db.w * 0.1f);
            float t2 = logf(w / db.z) * 5.f;
            float t3 = logf(h / db.w) * 5.f;
            float4 p = ((const float4*)locs_pred)[b * Dn + d];
            float e0 = fabsf(p.x - t0), e1 = fabsf(p.y - t1);
            float e2 = fabsf(p.z - t2), e3 = fabsf(p.w - t3);
            lsum += (e0 < 1.f ? 0.5f * e0 * e0 : e0 - 0.5f)
                  + (e1 < 1.f ? 0.5f * e1 * e1 : e1 - 0.5f)
                  + (e2 < 1.f ? 0.5f * e2 * e2 : e2 - 0.5f)
                  + (e3 < 1.f ? 0.5f * e3 * e3 : e3 - 0.5f);
        }
    }
    for (int off = 16; off; off >>= 1) {
        lsum += __shfl_down_sync(0xffffffffu, lsum, off);
        lcnt += __shfl_down_sync(0xffffffffu, lcnt, off);
    }
    if (lane == 0) { s_rs[warp] = lsum; s_rc[warp] = lcnt; }
    __syncthreads();
    if (tid == 0) {
        float ts = 0.f; int tc = 0;
        for (int w = 0; w < 16; w++) { ts += s_rs[w]; tc += s_rc[w]; }
        atomicAdd(&g_loc_sum, ts);
        g_npos[b] = tc;
        atomicAdd(&g_npos_tot, tc);
    }
}

// warp-per-box cross entropy over 81 classes
__global__ __launch_bounds__(256) void k_ce(const float* __restrict__ cls) {
    __shared__ float s_pos[8];
    const int warp = threadIdx.x >> 5, lane = threadIdx.x & 31;
    const long long bd = (long long)blockIdx.x * 8 + warp;
    float posce = 0.f;
    if (bd < (long long)Bn * Dn) {
        const float* p = cls + bd * Cn;
        float x0 = p[lane];
        float x1 = p[lane + 32];
        bool v2 = (lane + 64) < Cn;
        float x2 = v2 ? p[lane + 64] : -INFINITY;
        float m = fmaxf(x0, fmaxf(x1, x2));
        for (int off = 16; off; off >>= 1) m = fmaxf(m, __shfl_xor_sync(0xffffffffu, m, off));
        float s = expf(x0 - m) + expf(x1 - m) + (v2 ? expf(x2 - m) : 0.f);
        for (int off = 16; off; off >>= 1) s += __shfl_xor_sync(0xffffffffu, s, off);
        int t = g_tcls[bd];
        int src = t & 31, slot = t >> 5;
        float cand = (slot == 0) ? x0 : ((slot == 1) ? x1 : x2);
        float xt = __shfl_sync(0xffffffffu, cand, src);
        float ce = m + logf(s) - xt;
        if (lane == 0) {
            if (t != 0) { posce = ce; g_negce[bd] = 0.f; }
            else        { g_negce[bd] = ce; }
        }
    }
    if (lane == 0) s_pos[warp] = posce;
    __syncthreads();
    if (threadIdx.x == 0) {
        float s = 0.f;
        for (int w = 0; w < 8; w++) s += s_pos[w];
        if (s != 0.f) atomicAdd(&g_conf_pos, s);
    }
}

// per-batch exact top-K sum via 4-pass radix select (ce >= 0 -> float bits monotonic)
__global__ __launch_bounds__(256) void k_topk() {
    __shared__ float s_val[Dn];
    __shared__ unsigned int s_hist[256];
    __shared__ unsigned int s_bin;
    __shared__ int s_cum;
    __shared__ float s_rs[8];
    __shared__ int   s_rc[8];

    const int b = blockIdx.x, tid = threadIdx.x;
    for (int i = tid; i < Dn; i += 256) s_val[i] = g_negce[b * Dn + i];
    int K = 3 * g_npos[b];
    if (K > Dn) K = Dn;
    __syncthreads();
    if (K <= 0) return;

    unsigned int prefix = 0;
    int Krem = K;
    for (int shift = 24; shift >= 0; shift -= 8) {
        s_hist[tid] = 0;
        __syncthreads();
        unsigned int hmask = (shift == 24) ? 0u : (0xFFFFFFFFu << (shift + 8));
        for (int i = tid; i < Dn; i += 256) {
            unsigned int u = __float_as_uint(s_val[i]);
            if ((u & hmask) == prefix) atomicAdd(&s_hist[(u >> shift) & 255u], 1u);
        }
        __syncthreads();
        if (tid == 0) {
            int cum = 0; unsigned int bin = 0;
            for (int j = 255; j >= 0; j--) {
                int c = (int)s_hist[j];
                if (cum + c >= Krem) { bin = (unsigned int)j; break; }
                cum += c;
            }
            s_bin = bin; s_cum = cum;
        }
        __syncthreads();
        Krem -= s_cum;
        prefix |= (s_bin << shift);
        __syncthreads();
    }

    float kth = __uint_as_float(prefix);
    float ls = 0.f; int lc = 0;
    for (int i = tid; i < Dn; i += 256) {
        float v = s_val[i];
        if (v > kth) { ls += v; lc++; }
    }
    const int warp = tid >> 5, lane = tid & 31;
    for (int off = 16; off; off >>= 1) {
        ls += __shfl_down_sync(0xffffffffu, ls, off);
        lc += __shfl_down_sync(0xffffffffu, lc, off);
    }
    if (lane == 0) { s_rs[warp] = ls; s_rc[warp] = lc; }
    __syncthreads();
    if (tid == 0) {
        float ts = 0.f; int tc = 0;
        for (int w = 0; w < 8; w++) { ts += s_rs[w]; tc += s_rc[w]; }
        float total = ts + (float)(K - tc) * kth;
        atomicAdd(&g_conf_neg, total);
    }
}

__global__ void k_final(float* out) {
    float npt = (float)g_npos_tot;
    out[0] = g_loc_sum / (npt * 4.f);          // ALPHA = 1
    out[1] = (g_conf_neg + g_conf_pos) / npt;
}

extern "C" void kernel_launch(void* const* d_in, const int* in_sizes, int n_in,
                              void* d_out, int out_size) {
    const float* locs   = (const float*)d_in[0];
    const float* cls    = (const float*)d_in[1];
    const float* boxes  = (const float*)d_in[2];
    const int*   labels = (const int*)d_in[3];
    const float* dbox   = (const float*)d_in[4];

    k_init<<<1, 1>>>();
    k_match<<<Bn, 512>>>(locs, boxes, labels, dbox);
    int nblocks = (Bn * Dn + 7) / 8;
    k_ce<<<nblocks, 256>>>(cls);
    k_topk<<<Bn, 256>>>();
    k_final<<<1, 1>>>((float*)d_out);
}

// round 2
// speedup vs baseline: 1.1907x; 1.1907x over previous
#include <cuda_runtime.h>
#include <math.h>

#define Bn 64
#define Dn 8732
#define On 16
#define Cn 81

// ---- device scratch (no allocations allowed) ----
__device__ float g_loc_sum;
__device__ float g_conf_pos;
__device__ float g_conf_neg;
__device__ int   g_npos_tot;
__device__ int   g_npos[Bn];
__device__ float g_negce[Bn * Dn];
__device__ unsigned char g_tcls[Bn * Dn];

__global__ void k_init() {
    g_loc_sum = 0.f; g_conf_pos = 0.f; g_conf_neg = 0.f; g_npos_tot = 0;
}

// One block per batch element. Matching + target classes + fused SmoothL1.
// IoU comparisons are done DIVISION-FREE via cross-multiplication of
// (intersection, union) pairs; threshold iou>=0.5 becomes 2*inter>=union.
__global__ __launch_bounds__(512) void k_match(const float* __restrict__ locs_pred,
                                               const float* __restrict__ boxes,
                                               const int*   __restrict__ labels,
                                               const float* __restrict__ dboxes) {
    __shared__ unsigned char s_obj[Dn];
    __shared__ unsigned char s_fpos[Dn];     // positive flag (pre-force)
    __shared__ float s_bx[On][4];
    __shared__ float s_area[On];
    __shared__ int   s_lab[On];
    __shared__ float s_redn[On * 16];
    __shared__ float s_redd[On * 16];
    __shared__ int   s_redi[On * 16];
    __shared__ int   s_dobj[On];
    __shared__ float s_rs[16];
    __shared__ int   s_rc[16];

    const int b = blockIdx.x;
    const int tid = threadIdx.x;
    const int warp = tid >> 5, lane = tid & 31;

    if (tid < On * 4) ((float*)s_bx)[tid] = boxes[b * On * 4 + tid];
    if (tid < On)     s_lab[tid] = labels[b * On + tid];
    __syncthreads();
    if (tid < On) s_area[tid] = (s_bx[tid][2] - s_bx[tid][0]) * (s_bx[tid][3] - s_bx[tid][1]);
    __syncthreads();

    // per-object best over defaults, stored as (numer, denom, index)
    float ln[On], ld[On]; int li[On];
#pragma unroll
    for (int o = 0; o < On; o++) { ln[o] = -1.f; ld[o] = 1.f; li[o] = 0x7fffffff; }

    for (int d = tid; d < Dn; d += 512) {
        float4 db = ((const float4*)dboxes)[d];
        float dx1 = db.x - db.z * 0.5f, dy1 = db.y - db.w * 0.5f;
        float dx2 = db.x + db.z * 0.5f, dy2 = db.y + db.w * 0.5f;
        float darea = db.z * db.w;
        float bn = -1.f, bd_ = 1.f; int besto = 0;
#pragma unroll
        for (int o = 0; o < On; o++) {
            float ix = fminf(s_bx[o][2], dx2) - fmaxf(s_bx[o][0], dx1);
            float iy = fminf(s_bx[o][3], dy2) - fmaxf(s_bx[o][1], dy1);
            ix = fmaxf(ix, 0.f); iy = fmaxf(iy, 0.f);
            float inter = ix * iy;
            float uni = s_area[o] + darea - inter;
            // best over o for this default (first-max)
            if (inter * bd_ > bn * uni) { bn = inter; bd_ = uni; besto = o; }
            // best over d for this object (ascending d -> first-max)
            if (inter * ld[o] > ln[o] * uni) { ln[o] = inter; ld[o] = uni; li[o] = d; }
        }
        s_obj[d] = (unsigned char)besto;
        s_fpos[d] = (2.f * bn >= bd_) ? 1 : 0;
    }

    // reduce per-object best across threads (tie -> smaller default index)
#pragma unroll
    for (int o = 0; o < On; o++) {
        float vn = ln[o], vd = ld[o]; int vi = li[o];
        for (int off = 16; off; off >>= 1) {
            float on_ = __shfl_down_sync(0xffffffffu, vn, off);
            float od_ = __shfl_down_sync(0xffffffffu, vd, off);
            int   oi  = __shfl_down_sync(0xffffffffu, vi, off);
            float a = on_ * vd, c = vn * od_;
            if (a > c || (a == c && oi < vi)) { vn = on_; vd = od_; vi = oi; }
        }
        if (lane == 0) { s_redn[o * 16 + warp] = vn; s_redd[o * 16 + warp] = vd; s_redi[o * 16 + warp] = vi; }
    }
    __syncthreads();
    if (tid < On) {
        float vn = s_redn[tid * 16], vd = s_redd[tid * 16]; int vi = s_redi[tid * 16];
        for (int w = 1; w < 16; w++) {
            float on_ = s_redn[tid * 16 + w], od_ = s_redd[tid * 16 + w];
            int oi = s_redi[tid * 16 + w];
            float a = on_ * vd, c = vn * od_;
            if (a > c || (a == c && oi < vi)) { vn = on_; vd = od_; vi = oi; }
        }
        s_dobj[tid] = vi;
    }
    __syncthreads();
    if (tid == 0) {
        for (int o = 0; o < On; o++) {       // sequential: duplicate best-default -> last object wins
            int d = s_dobj[o];
            s_obj[d] = (unsigned char)o;
            s_fpos[d] = 1;
        }
    }
    __syncthreads();

    // targets + fused SmoothL1 on positives
    float lsum = 0.f; int lcnt = 0;
    for (int d = tid; d < Dn; d += 512) {
        int o = s_obj[d];
        int lab = s_fpos[d] ? s_lab[o] : 0;
        g_tcls[b * Dn + d] = (unsigned char)lab;
        if (lab != 0) {
            lcnt++;
            float4 db = ((const float4*)dboxes)[d];
            float bx1 = s_bx[o][0], by1 = s_bx[o][1], bx2 = s_bx[o][2], by2 = s_bx[o][3];
            float cx = 0.5f * (bx1 + bx2), cy = 0.5f * (by1 + by2);
            float w = bx2 - bx1, h = by2 - by1;
            float t0 = (cx - db.x) / (db.z * 0.1f);
            float t1 = (cy - db.y) / (db.w * 0.1f);
            float t2 = logf(w / db.z) * 5.f;
            float t3 = logf(h / db.w) * 5.f;
            float4 p = ((const float4*)locs_pred)[b * Dn + d];
            float e0 = fabsf(p.x - t0), e1 = fabsf(p.y - t1);
            float e2 = fabsf(p.z - t2), e3 = fabsf(p.w - t3);
            lsum += (e0 < 1.f ? 0.5f * e0 * e0 : e0 - 0.5f)
                  + (e1 < 1.f ? 0.5f * e1 * e1 : e1 - 0.5f)
                  + (e2 < 1.f ? 0.5f * e2 * e2 : e2 - 0.5f)
                  + (e3 < 1.f ? 0.5f * e3 * e3 : e3 - 0.5f);
        }
    }
    for (int off = 16; off; off >>= 1) {
        lsum += __shfl_down_sync(0xffffffffu, lsum, off);
        lcnt += __shfl_down_sync(0xffffffffu, lcnt, off);
    }
    if (lane == 0) { s_rs[warp] = lsum; s_rc[warp] = lcnt; }
    __syncthreads();
    if (tid == 0) {
        float ts = 0.f; int tc = 0;
        for (int w = 0; w < 16; w++) { ts += s_rs[w]; tc += s_rc[w]; }
        atomicAdd(&g_loc_sum, ts);
        g_npos[b] = tc;
        atomicAdd(&g_npos_tot, tc);
    }
}

// warp-per-box cross entropy over 81 classes (fast exp/log)
__global__ __launch_bounds__(256) void k_ce(const float* __restrict__ cls) {
    __shared__ float s_pos[8];
    const int warp = threadIdx.x >> 5, lane = threadIdx.x & 31;
    const long long bd = (long long)blockIdx.x * 8 + warp;
    float posce = 0.f;
    if (bd < (long long)Bn * Dn) {
        const float* p = cls + bd * Cn;
        float x0 = p[lane];
        float x1 = p[lane + 32];
        bool v2 = (lane + 64) < Cn;
        float x2 = v2 ? p[lane + 64] : -INFINITY;
        float m = fmaxf(x0, fmaxf(x1, x2));
        for (int off = 16; off; off >>= 1) m = fmaxf(m, __shfl_xor_sync(0xffffffffu, m, off));
        float s = __expf(x0 - m) + __expf(x1 - m) + (v2 ? __expf(x2 - m) : 0.f);
        for (int off = 16; off; off >>= 1) s += __shfl_xor_sync(0xffffffffu, s, off);
        int t = g_tcls[bd];
        int src = t & 31, slot = t >> 5;
        float cand = (slot == 0) ? x0 : ((slot == 1) ? x1 : x2);
        float xt = __shfl_sync(0xffffffffu, cand, src);
        float ce = m + __logf(s) - xt;
        if (lane == 0) {
            if (t != 0) { posce = ce; g_negce[bd] = 0.f; }
            else        { g_negce[bd] = ce; }
        }
    }
    if (lane == 0) s_pos[warp] = posce;
    __syncthreads();
    if (threadIdx.x == 0) {
        float s = 0.f;
        for (int w = 0; w < 8; w++) s += s_pos[w];
        if (s != 0.f) atomicAdd(&g_conf_pos, s);
    }
}

// per-batch exact top-K sum via 4-pass radix select with warp-aggregated
// histogram atomics (match_any) to kill same-bin contention.
__global__ __launch_bounds__(256) void k_topk() {
    __shared__ float s_val[Dn];
    __shared__ unsigned int s_hist[256];
    __shared__ unsigned int s_bin;
    __shared__ int s_cum;
    __shared__ float s_rs[8];
    __shared__ int   s_rc[8];

    const int b = blockIdx.x, tid = threadIdx.x;
    const int lane = tid & 31;
    for (int i = tid; i < Dn; i += 256) s_val[i] = g_negce[b * Dn + i];
    int K = 3 * g_npos[b];
    if (K > Dn) K = Dn;
    __syncthreads();
    if (K <= 0) return;

    unsigned int prefix = 0;
    int Krem = K;
    for (int shift = 24; shift >= 0; shift -= 8) {
        s_hist[tid] = 0;
        __syncthreads();
        unsigned int hmask = (shift == 24) ? 0u : (0xFFFFFFFFu << (shift + 8));
        for (int base = 0; base < Dn; base += 256) {
            int i = base + tid;
            bool pred = false;
            unsigned int bin = 0;
            if (i < Dn) {
                unsigned int u = __float_as_uint(s_val[i]);
                if ((u & hmask) == prefix) { pred = true; bin = (u >> shift) & 255u; }
            }
            unsigned int act = __ballot_sync(0xffffffffu, pred);
            if (pred) {
                unsigned int peers = __match_any_sync(act, bin);
                if (lane == (__ffs(peers) - 1))
                    atomicAdd(&s_hist[bin], (unsigned int)__popc(peers));
            }
        }
        __syncthreads();
        if (tid == 0) {
            int cum = 0; unsigned int bin = 0;
            for (int j = 255; j >= 0; j--) {
                int c = (int)s_hist[j];
                if (cum + c >= Krem) { bin = (unsigned int)j; break; }
                cum += c;
            }
            s_bin = bin; s_cum = cum;
        }
        __syncthreads();
        Krem -= s_cum;
        prefix |= (s_bin << shift);
        __syncthreads();
    }

    float kth = __uint_as_float(prefix);
    float ls = 0.f; int lc = 0;
    for (int i = tid; i < Dn; i += 256) {
        float v = s_val[i];
        if (v > kth) { ls += v; lc++; }
    }
    const int warp = tid >> 5;
    for (int off = 16; off; off >>= 1) {
        ls += __shfl_down_sync(0xffffffffu, ls, off);
        lc += __shfl_down_sync(0xffffffffu, lc, off);
    }
    if (lane == 0) { s_rs[warp] = ls; s_rc[warp] = lc; }
    __syncthreads();
    if (tid == 0) {
        float ts = 0.f; int tc = 0;
        for (int w = 0; w < 8; w++) { ts += s_rs[w]; tc += s_rc[w]; }
        float total = ts + (float)(K - tc) * kth;
        atomicAdd(&g_conf_neg, total);
    }
}

__global__ void k_final(float* out) {
    float npt = (float)g_npos_tot;
    out[0] = g_loc_sum / (npt * 4.f);          // ALPHA = 1
    out[1] = (g_conf_neg + g_conf_pos) / npt;
}

extern "C" void kernel_launch(void* const* d_in, const int* in_sizes, int n_in,
                              void* d_out, int out_size) {
    const float* locs   = (const float*)d_in[0];
    const float* cls    = (const float*)d_in[1];
    const float* boxes  = (const float*)d_in[2];
    const int*   labels = (const int*)d_in[3];
    const float* dbox   = (const float*)d_in[4];

    k_init<<<1, 1>>>();
    k_match<<<Bn, 512>>>(locs, boxes, labels, dbox);
    int nblocks = (Bn * Dn + 7) / 8;
    k_ce<<<nblocks, 256>>>(cls);
    k_topk<<<Bn, 256>>>();
    k_final<<<1, 1>>>((float*)d_out);
}

// round 3
// speedup vs baseline: 1.6987x; 1.4266x over previous
#include <cuda_runtime.h>
#include <math.h>

#define Bn 64
#define Dn 8732
#define Hn 4366      // Dn/2, defaults per match block
#define On 16
#define Cn 81

// ---- device scratch (no allocations allowed) ----
__device__ float g_loc_sum;
__device__ float g_conf_pos;
__device__ float g_conf_neg;
__device__ int   g_npos[Bn];
__device__ unsigned long long g_objbest[Bn * On];  // packed (iou_bits<<32)|(~d)
__device__ float g_negce[Bn * Dn];
__device__ unsigned char g_obj[Bn * Dn];
__device__ unsigned char g_fpos[Bn * Dn];

__global__ void k_init() {
    if (threadIdx.x == 0) { g_loc_sum = 0.f; g_conf_pos = 0.f; g_conf_neg = 0.f; }
    if (threadIdx.x < Bn) g_npos[threadIdx.x] = 0;
    g_objbest[threadIdx.x] = 0ull;   // 1024 threads == Bn*On
}

// 2 blocks per batch element; block handles half the defaults.
// Division-free (inter,union) cross-multiplication comparisons.
__global__ __launch_bounds__(512) void k_match(const float* __restrict__ boxes,
                                               const float* __restrict__ dboxes) {
    __shared__ float s_bx[On][4];
    __shared__ float s_area[On];
    __shared__ float s_redn[On * 16];
    __shared__ float s_redd[On * 16];
    __shared__ int   s_redi[On * 16];

    const int b    = blockIdx.x >> 1;
    const int half = blockIdx.x & 1;
    const int tid  = threadIdx.x;
    const int warp = tid >> 5, lane = tid & 31;
    const int d0 = half * Hn, d1 = d0 + Hn;

    if (tid < On * 4) ((float*)s_bx)[tid] = boxes[b * On * 4 + tid];
    __syncthreads();
    if (tid < On) s_area[tid] = (s_bx[tid][2] - s_bx[tid][0]) * (s_bx[tid][3] - s_bx[tid][1]);
    __syncthreads();

    float ln[On], ld[On]; int li[On];
#pragma unroll
    for (int o = 0; o < On; o++) { ln[o] = -1.f; ld[o] = 1.f; li[o] = 0x7fffffff; }

    for (int d = d0 + tid; d < d1; d += 512) {
        float4 db = ((const float4*)dboxes)[d];
        float dx1 = db.x - db.z * 0.5f, dy1 = db.y - db.w * 0.5f;
        float dx2 = db.x + db.z * 0.5f, dy2 = db.y + db.w * 0.5f;
        float darea = db.z * db.w;
        float bn = -1.f, bd_ = 1.f; int besto = 0;
#pragma unroll
        for (int o = 0; o < On; o++) {
            float ix = fminf(s_bx[o][2], dx2) - fmaxf(s_bx[o][0], dx1);
            float iy = fminf(s_bx[o][3], dy2) - fmaxf(s_bx[o][1], dy1);
            ix = fmaxf(ix, 0.f); iy = fmaxf(iy, 0.f);
            float inter = ix * iy;
            float uni = s_area[o] + darea - inter;
            if (inter * bd_ > bn * uni) { bn = inter; bd_ = uni; besto = o; }   // first-max over o
            if (inter * ld[o] > ln[o] * uni) { ln[o] = inter; ld[o] = uni; li[o] = d; } // first-max over d
        }
        g_obj[b * Dn + d]  = (unsigned char)besto;
        g_fpos[b * Dn + d] = (2.f * bn >= bd_) ? 1 : 0;
    }

    // block-level per-object best (tie -> smaller default index)
#pragma unroll
    for (int o = 0; o < On; o++) {
        float vn = ln[o], vd = ld[o]; int vi = li[o];
        for (int off = 16; off; off >>= 1) {
            float on_ = __shfl_down_sync(0xffffffffu, vn, off);
            float od_ = __shfl_down_sync(0xffffffffu, vd, off);
            int   oi  = __shfl_down_sync(0xffffffffu, vi, off);
            float a = on_ * vd, c = vn * od_;
            if (a > c || (a == c && oi < vi)) { vn = on_; vd = od_; vi = oi; }
        }
        if (lane == 0) { s_redn[o * 16 + warp] = vn; s_redd[o * 16 + warp] = vd; s_redi[o * 16 + warp] = vi; }
    }
    __syncthreads();
    if (tid < On) {
        float vn = s_redn[tid * 16], vd = s_redd[tid * 16]; int vi = s_redi[tid * 16];
        for (int w = 1; w < 16; w++) {
            float on_ = s_redn[tid * 16 + w], od_ = s_redd[tid * 16 + w];
            int oi = s_redi[tid * 16 + w];
            float a = on_ * vd, c = vn * od_;
            if (a > c || (a == c && oi < vi)) { vn = on_; vd = od_; vi = oi; }
        }
        float iou = vn / vd;   // 16 divisions per block total
        unsigned long long pk = ((unsigned long long)__float_as_uint(iou) << 32)
                              | (unsigned long long)(0xFFFFFFFFu - (unsigned int)vi);
        atomicMax(&g_objbest[b * On + tid], pk);
    }
}

// apply forced matches: sequential over objects (last wins, matching .at[].set)
__global__ void k_force() {
    const int b = blockIdx.x;
    if (threadIdx.x == 0) {
        for (int o = 0; o < On; o++) {
            unsigned long long pk = g_objbest[b * On + o];
            int d = (int)(0xFFFFFFFFu - (unsigned int)(pk & 0xFFFFFFFFull));
            g_obj[b * Dn + d]  = (unsigned char)o;
            g_fpos[b * Dn + d] = 1;
        }
    }
}

// warp-per-box: label + cross entropy + (positives) SmoothL1 loc loss + npos
__global__ __launch_bounds__(256) void k_ce(const float* __restrict__ cls,
                                            const float* __restrict__ locs_pred,
                                            const float* __restrict__ boxes,
                                            const int*   __restrict__ labels,
                                            const float* __restrict__ dboxes) {
    const int warp = threadIdx.x >> 5, lane = threadIdx.x & 31;
    const int bd = blockIdx.x * 8 + warp;     // grid sized exactly: Bn*Dn/8
    const int b = bd / Dn, d = bd - b * Dn;

    int lab = 0, o = 0;
    if (lane == 0) {
        o = g_obj[bd];
        lab = g_fpos[bd] ? labels[b * On + o] : 0;
    }
    lab = __shfl_sync(0xffffffffu, lab, 0);

    const float* p = cls + (long long)bd * Cn;
    float x0 = p[lane];
    float x1 = p[lane + 32];
    bool v2 = (lane + 64) < Cn;
    float x2 = v2 ? p[lane + 64] : -INFINITY;
    float m = fmaxf(x0, fmaxf(x1, x2));
    for (int off = 16; off; off >>= 1) m = fmaxf(m, __shfl_xor_sync(0xffffffffu, m, off));
    float s = __expf(x0 - m) + __expf(x1 - m) + (v2 ? __expf(x2 - m) : 0.f);
    for (int off = 16; off; off >>= 1) s += __shfl_xor_sync(0xffffffffu, s, off);
    int src = lab & 31, slot = lab >> 5;
    float cand = (slot == 0) ? x0 : ((slot == 1) ? x1 : x2);
    float xt = __shfl_sync(0xffffffffu, cand, src);
    float ce = m + __logf(s) - xt;

    if (lane == 0) {
        if (lab != 0) {
            g_negce[bd] = 0.f;
            atomicAdd(&g_conf_pos, ce);
            atomicAdd(&g_npos[b], 1);
            // SmoothL1 on this positive
            float4 db = ((const float4*)dboxes)[d];
            const float* bx = boxes + (b * On + o) * 4;
            float bx1 = bx[0], by1 = bx[1], bx2 = bx[2], by2 = bx[3];
            float cx = 0.5f * (bx1 + bx2), cy = 0.5f * (by1 + by2);
            float w = bx2 - bx1, h = by2 - by1;
            float t0 = (cx - db.x) / (db.z * 0.1f);
            float t1 = (cy - db.y) / (db.w * 0.1f);
            float t2 = logf(w / db.z) * 5.f;
            float t3 = logf(h / db.w) * 5.f;
            float4 pr = ((const float4*)locs_pred)[bd];
            float e0 = fabsf(pr.x - t0), e1 = fabsf(pr.y - t1);
            float e2 = fabsf(pr.z - t2), e3 = fabsf(pr.w - t3);
            float sl = (e0 < 1.f ? 0.5f * e0 * e0 : e0 - 0.5f)
                     + (e1 < 1.f ? 0.5f * e1 * e1 : e1 - 0.5f)
                     + (e2 < 1.f ? 0.5f * e2 * e2 : e2 - 0.5f)
                     + (e3 < 1.f ? 0.5f * e3 * e3 : e3 - 0.5f);
            atomicAdd(&g_loc_sum, sl);
        } else {
            g_negce[bd] = ce;
        }
    }
}

// per-batch exact top-K sum via 4-pass radix select; parallel bin selection.
__global__ __launch_bounds__(1024) void k_topk() {
    __shared__ float s_val[Dn];
    __shared__ unsigned int s_hist[256];
    __shared__ unsigned int s_bin;
    __shared__ int s_cum;
    __shared__ float s_rs[32];
    __shared__ int   s_rc[32];

    const int b = blockIdx.x, tid = threadIdx.x;
    const int warp = tid >> 5, lane = tid & 31;

    // coalesced float4 load into shared (Dn % 4 == 0, base aligned)
    const float4* src = (const float4*)(g_negce + b * Dn);
    for (int i = tid; i < Dn / 4; i += 1024) ((float4*)s_val)[i] = src[i];
    int K = 3 * g_npos[b];
    if (K > Dn) K = Dn;
    __syncthreads();
    if (K <= 0) return;

    unsigned int prefix = 0;
    int Krem = K;
    for (int shift = 24; shift >= 0; shift -= 8) {
        if (tid < 256) s_hist[tid] = 0;
        __syncthreads();
        unsigned int hmask = (shift == 24) ? 0u : (0xFFFFFFFFu << (shift + 8));
        for (int i = tid; i < Dn; i += 1024) {
            unsigned int u = __float_as_uint(s_val[i]);
            if ((u & hmask) == prefix) atomicAdd(&s_hist[(u >> shift) & 255u], 1u);
        }
        __syncthreads();
        // parallel selection: warp 0, 8 bins per lane, suffix scan via shfl
        if (warp == 0) {
            unsigned int c[8]; int local = 0;
            int base = lane * 8;
#pragma unroll
            for (int k = 0; k < 8; k++) { c[k] = s_hist[base + k]; local += (int)c[k]; }
            int incl = local;
#pragma unroll
            for (int off = 1; off < 32; off <<= 1) {
                int v = __shfl_down_sync(0xffffffffu, incl, off);
                if (lane + off < 32) incl += v;
            }
            int excl = incl - local;      // sum over bins owned by lanes > lane
            if (excl < Krem && incl >= Krem) {
                int cum = excl;
#pragma unroll
                for (int j = 7; j >= 0; j--) {
                    if (cum + (int)c[j] >= Krem) { s_bin = (unsigned int)(base + j); s_cum = cum; break; }
                    cum += (int)c[j];
                }
            }
        }
        __syncthreads();
        Krem -= s_cum;
        prefix |= (s_bin << shift);
        __syncthreads();
    }

    float kth = __uint_as_float(prefix);
    float ls = 0.f; int lc = 0;
    for (int i = tid; i < Dn; i += 1024) {
        float v = s_val[i];
        if (v > kth) { ls += v; lc++; }
    }
    for (int off = 16; off; off >>= 1) {
        ls += __shfl_down_sync(0xffffffffu, ls, off);
        lc += __shfl_down_sync(0xffffffffu, lc, off);
    }
    if (lane == 0) { s_rs[warp] = ls; s_rc[warp] = lc; }
    __syncthreads();
    if (tid == 0) {
        float ts = 0.f; int tc = 0;
        for (int w = 0; w < 32; w++) { ts += s_rs[w]; tc += s_rc[w]; }
        atomicAdd(&g_conf_neg, ts + (float)(K - tc) * kth);
    }
}

__global__ void k_final(float* out) {
    int npt = 0;
    for (int b = 0; b < Bn; b++) npt += g_npos[b];
    float f = (float)npt;
    out[0] = g_loc_sum / (f * 4.f);            // ALPHA = 1
    out[1] = (g_conf_neg + g_conf_pos) / f;
}

extern "C" void kernel_launch(void* const* d_in, const int* in_sizes, int n_in,
                              void* d_out, int out_size) {
    const float* locs   = (const float*)d_in[0];
    const float* cls    = (const float*)d_in[1];
    const float* boxes  = (const float*)d_in[2];
    const int*   labels = (const int*)d_in[3];
    const float* dbox   = (const float*)d_in[4];

    k_init<<<1, 1024>>>();
    k_match<<<2 * Bn, 512>>>(boxes, dbox);
    k_force<<<Bn, 32>>>();
    k_ce<<<(Bn * Dn) / 8, 256>>>(cls, locs, boxes, labels, dbox);
    k_topk<<<Bn, 1024>>>();
    k_final<<<1, 1>>>((float*)d_out);
}